// round 7
// baseline (speedup 1.0000x reference)
#include <cuda_runtime.h>
#include <math.h>

// Problem constants (fixed shapes): B=8, S=4, Nq=1024, PS=16, H=W=256
#define NPATCH 1024
#define NPROB  32          // B*S
#define SDIM   4
#define WIMG   256
#define EPSB   1e-4f
#define MIN_CORR 6
#define USCALE  (1.0f/256.0f)   // pixel-coordinate scaling for conditioning
#define BLKS_PER_PROB 128       // 8 patches per block

// per-block partial moments: [prob][41][128 blocks]  (40 moments + count)
__device__ float g_part[NPROB * 41 * BLKS_PER_PROB];
__device__ float g_per[NPROB];
__device__ float g_cnt[NPROB];
__device__ int   g_ticket = 0;

// ---------------------------------------------------------------------------
// Kernel 1: fused stream. Each block = 8 patches of one problem.
//  - 8 lanes gather depth + compute X_obj (early, hidden under the stream)
//  - each warp streams its patch's 256 b/w values, reduces w_patch
//  - lanes compute the 40 per-patch moment products, block writes a 41-float
//    partial (40 moments + mask count) to g_part.
// ---------------------------------------------------------------------------
__global__ __launch_bounds__(256) void k_stream(
    const float* __restrict__ db, const float* __restrict__ dw,
    const int*   __restrict__ pcls,
    const float* __restrict__ Kmat,   // (B,5,3,3)
    const float* __restrict__ poses,  // (B,5,4,4)
    const float* __restrict__ depth)  // (B,S,256,256)
{
    int blk  = blockIdx.x;            // 0..4095
    int prob = blk >> 7;              // 128 blocks per problem
    int tid  = threadIdx.x;
    int w    = tid >> 5, lane = tid & 31;

    __shared__ float sX[8][3];
    __shared__ int   sValid[8];
    __shared__ float sRed[8][40];
    __shared__ int   sCnt[8];

    // ---- issue the big streaming loads FIRST (4 float4 per thread) ----
    int patch = blk * 8 + w;                          // global patch id
    const float4* b4 = (const float4*)db + (size_t)patch * 64;
    const float4* w4 = (const float4*)dw + (size_t)patch * 64;
    float4 b0 = __ldcs(b4 + lane);
    float4 b1 = __ldcs(b4 + 32 + lane);
    float4 w0 = __ldcs(w4 + lane);
    float4 w1 = __ldcs(w4 + 32 + lane);

    // ---- 8 lanes: per-patch geometry (gather + transform) ----
    if (tid < 8) {
        int bb = prob >> 2, ss = prob & 3;
        int n  = ((blk & 127) << 3) + tid;            // patch index within problem
        int cls = __ldg(&pcls[prob * NPATCH + n]);
        bool valid = (cls >= 0) && (cls < NPATCH);
        int buddy = min(max(cls, 0), NPATCH - 1);
        int bx2 = buddy & 31, by2 = buddy >> 5;
        float d = __ldg(&depth[(size_t)prob * (WIMG * WIMG)
                               + (by2 * 8 + 4) * WIMG + (bx2 * 8 + 4)]);
        const float* Kt = Kmat  + ((size_t)bb * 5 + ss + 1) * 9;
        const float* Ps = poses + ((size_t)bb * 5 + ss + 1) * 16;
        float fx = __ldg(Kt + 0), fy = __ldg(Kt + 4);
        float cx = __ldg(Kt + 2), cy = __ldg(Kt + 5);
        float R00=__ldg(Ps+0), R01=__ldg(Ps+1), R02=__ldg(Ps+2),  t0p=__ldg(Ps+3);
        float R10=__ldg(Ps+4), R11=__ldg(Ps+5), R12=__ldg(Ps+6),  t1p=__ldg(Ps+7);
        float R20=__ldg(Ps+8), R21=__ldg(Ps+9), R22=__ldg(Ps+10), t2p=__ldg(Ps+11);
        float ti0 = -(R00*t0p + R10*t1p + R20*t2p);
        float ti1 = -(R01*t0p + R11*t1p + R21*t2p);
        float ti2 = -(R02*t0p + R12*t1p + R22*t2p);
        float cxj = (float)(bx2 * 8 + 4);
        float cyj = (float)(by2 * 8 + 4);
        float xn = (cxj - cx) / fx;
        float yn = (cyj - cy) / fy;
        float Xc0 = xn * d, Xc1 = yn * d, Xc2 = d;
        sX[tid][0] = R00*Xc0 + R10*Xc1 + R20*Xc2 + ti0;
        sX[tid][1] = R01*Xc0 + R11*Xc1 + R21*Xc2 + ti1;
        sX[tid][2] = R02*Xc0 + R12*Xc1 + R22*Xc2 + ti2;
        sValid[tid] = valid ? 1 : 0;
    }

    // ---- patch mean of w/(max(b,eps)+eps) ----
    float acc = 0.f;
    acc += __fdividef(w0.x, fmaxf(b0.x, EPSB) + EPSB);
    acc += __fdividef(w0.y, fmaxf(b0.y, EPSB) + EPSB);
    acc += __fdividef(w0.z, fmaxf(b0.z, EPSB) + EPSB);
    acc += __fdividef(w0.w, fmaxf(b0.w, EPSB) + EPSB);
    acc += __fdividef(w1.x, fmaxf(b1.x, EPSB) + EPSB);
    acc += __fdividef(w1.y, fmaxf(b1.y, EPSB) + EPSB);
    acc += __fdividef(w1.z, fmaxf(b1.z, EPSB) + EPSB);
    acc += __fdividef(w1.w, fmaxf(b1.w, EPSB) + EPSB);
#pragma unroll
    for (int o = 16; o; o >>= 1) acc += __shfl_xor_sync(0xffffffffu, acc, o);
    float wn = acc * (1.f / 256.f);                  // all lanes hold it

    __syncthreads();                                 // sX/sValid ready

    bool msk = (sValid[w] != 0) && (wn > 0.f);
    float wm = msk ? wn : 0.f;
    float X = sX[w][0], Y = sX[w][1], Z = sX[w][2];
    int   n  = ((blk & 127) << 3) + w;
    float u  = (float)((n & 31) * 8 + 4) * USCALE;
    float v  = (float)((n >> 5) * 8 + 4) * USCALE;

    // moment m = i*10 + j : mm[i] * P10[j]
    float mm0 = wm, mm1 = wm * u, mm2 = wm * v, mm3 = wm * (u*u + v*v);
    float P10[10];
    P10[0] = 1.f; P10[1] = X; P10[2] = Y; P10[3] = Z;
    P10[4] = X*X; P10[5] = X*Y; P10[6] = X*Z;
    P10[7] = Y*Y; P10[8] = Y*Z; P10[9] = Z*Z;

    {   // lane computes moment 'lane'; lanes 0..7 also moment lane+32
        int m = lane;
        int i = m / 10, j = m - i * 10;
        float mi = (i == 0) ? mm0 : (i == 1) ? mm1 : (i == 2) ? mm2 : mm3;
        sRed[w][m] = mi * P10[j];
        if (lane < 8) {
            int m2 = lane + 32;
            int i2 = m2 / 10, j2 = m2 - i2 * 10;
            float mi2 = (i2 == 1) ? mm1 : (i2 == 2) ? mm2 : mm3;
            sRed[w][m2] = mi2 * P10[j2];
        }
        if (lane == 0) sCnt[w] = msk ? 1 : 0;
    }
    __syncthreads();

    if (tid < 40) {
        float p = 0.f;
#pragma unroll
        for (int k = 0; k < 8; k++) p += sRed[k][tid];
        g_part[((size_t)prob * 41 + tid) * BLKS_PER_PROB + (blk & 127)] = p;
    } else if (tid == 40) {
        int c = 0;
#pragma unroll
        for (int k = 0; k < 8; k++) c += sCnt[k];
        g_part[((size_t)prob * 41 + 40) * BLKS_PER_PROB + (blk & 127)] = (float)c;
    }
}

// ---------------------------------------------------------------------------
// f32 LDL^T helpers (no sqrt, fast division)
// ---------------------------------------------------------------------------
__device__ __forceinline__ void ldl4_factor(const float S[4][4],
                                            float L[4][4], float rD[4]) {
    float D[4];
#pragma unroll
    for (int j = 0; j < 4; j++) {
        float d = S[j][j];
#pragma unroll
        for (int k = 0; k < 4; k++) if (k < j) d -= L[j][k] * L[j][k] * D[k];
        D[j] = d; rD[j] = __fdividef(1.0f, d);
#pragma unroll
        for (int i = 0; i < 4; i++) if (i > j) {
            float v = S[i][j];
#pragma unroll
            for (int k = 0; k < 4; k++) if (k < j) v -= L[i][k] * D[k] * L[j][k];
            L[i][j] = v * rD[j];
        }
    }
}
__device__ __forceinline__ void ldl4_solve(const float L[4][4], const float rD[4],
                                           const float y[4], float x[4]) {
    float z[4];
#pragma unroll
    for (int i = 0; i < 4; i++) {
        float v = y[i];
#pragma unroll
        for (int k = 0; k < 4; k++) if (k < i) v -= L[i][k] * z[k];
        z[i] = v;
    }
#pragma unroll
    for (int i = 0; i < 4; i++) z[i] *= rD[i];
#pragma unroll
    for (int i = 3; i >= 0; i--) {
        float v = z[i];
#pragma unroll
        for (int k = 0; k < 4; k++) if (k > i) v -= L[k][i] * x[k];
        x[i] = v;
    }
}
__device__ __forceinline__ void ldl3_solve(const float S[3][3], const float y[3], float x[3]) {
    float L[3][3], D[3], rD[3];
#pragma unroll
    for (int j = 0; j < 3; j++) {
        float d = S[j][j];
#pragma unroll
        for (int k = 0; k < 3; k++) if (k < j) d -= L[j][k] * L[j][k] * D[k];
        D[j] = d; rD[j] = __fdividef(1.0f, d);
#pragma unroll
        for (int i = 0; i < 3; i++) if (i > j) {
            float v = S[i][j];
#pragma unroll
            for (int k = 0; k < 3; k++) if (k < j) v -= L[i][k] * D[k] * L[j][k];
            L[i][j] = v * rD[j];
        }
    }
    float z[3];
#pragma unroll
    for (int i = 0; i < 3; i++) {
        float v = y[i];
#pragma unroll
        for (int k = 0; k < 3; k++) if (k < i) v -= L[i][k] * z[k];
        z[i] = v;
    }
#pragma unroll
    for (int i = 0; i < 3; i++) z[i] *= rD[i];
#pragma unroll
    for (int i = 2; i >= 0; i--) {
        float v = z[i];
#pragma unroll
        for (int k = 0; k < 3; k++) if (k > i) v -= L[k][i] * x[k];
        x[i] = v;
    }
}

// ---------------------------------------------------------------------------
// Kernel 2: per-problem partial reduction (128-way) + f32 tail + fused final
// scalar via last-block ticket.
// ---------------------------------------------------------------------------
__global__ __launch_bounds__(96) void k_solve(
    const float* __restrict__ Kmat,     // (B,5,3,3)
    const float* __restrict__ gt_pose,  // (B,S,4,4)
    float* __restrict__ out)
{
    int prob = blockIdx.x;
    int tid = threadIdx.x;

    __shared__ float sMo[41];
    __shared__ float sKq[9], sGt[16];

    if (tid < 41) {
        const float4* p4 = (const float4*)(g_part + ((size_t)prob * 41 + tid) * BLKS_PER_PROB);
        float s = 0.f;
#pragma unroll
        for (int k = 0; k < 32; k++) {
            float4 vv = p4[k];
            s += vv.x + vv.y + vv.z + vv.w;
        }
        sMo[tid] = s;
    } else if (tid < 50) {
        int bb = prob >> 2;
        sKq[tid - 41] = Kmat[(size_t)bb * 45 + (tid - 41)];
    } else if (tid < 66) {
        sGt[tid - 50] = gt_pose[(size_t)prob * 16 + (tid - 50)];
    }
    __syncthreads();

    if (tid == 0) {
        const float* mw = sMo;
        const float* mu = sMo + 10;
        const float* mv = sMo + 20;
        const float* mq = sMo + 30;
        const int SYM[3][3] = {{4,5,6},{5,7,8},{6,8,9}};

        float S[4][4], Ub[4][3], Vb[4][3], Cm[3][3], ru[4], rv[4], rc[3];
#pragma unroll
        for (int r = 0; r < 4; r++)
#pragma unroll
            for (int c = 0; c < 4; c++) {
                float vv;
                if (r < 3 && c < 3)        vv = mw[SYM[r][c]];
                else if (r == 3 && c == 3) vv = mw[0];
                else if (r == 3)           vv = mw[1 + c];
                else                       vv = mw[1 + r];
                S[r][c] = vv;
            }
#pragma unroll
        for (int i = 0; i < 4; i++) S[i][i] += 1e-6f;
#pragma unroll
        for (int r = 0; r < 4; r++)
#pragma unroll
            for (int c = 0; c < 3; c++) {
                Ub[r][c] = -((r < 3) ? mu[SYM[r][c]] : mu[1 + c]);
                Vb[r][c] = -((r < 3) ? mv[SYM[r][c]] : mv[1 + c]);
            }
#pragma unroll
        for (int r = 0; r < 3; r++)
#pragma unroll
            for (int c = 0; c < 3; c++) Cm[r][c] = mq[SYM[r][c]];
#pragma unroll
        for (int i = 0; i < 3; i++) Cm[i][i] += 1e-6f;
#pragma unroll
        for (int r = 0; r < 4; r++) {
            ru[r] = (r < 3) ? mu[1 + r] : mu[0];
            rv[r] = (r < 3) ? mv[1 + r] : mv[0];
        }
#pragma unroll
        for (int c = 0; c < 3; c++) rc[c] = -mq[1 + c];

        float L4[4][4], rD4[4];
        ldl4_factor(S, L4, rD4);

        float YU[4][3], YV[4][3], ya[4], yb[4];
#pragma unroll
        for (int c = 0; c < 3; c++) {
            float col[4], sol[4];
#pragma unroll
            for (int r = 0; r < 4; r++) col[r] = Ub[r][c];
            ldl4_solve(L4, rD4, col, sol);
#pragma unroll
            for (int r = 0; r < 4; r++) YU[r][c] = sol[r];
#pragma unroll
            for (int r = 0; r < 4; r++) col[r] = Vb[r][c];
            ldl4_solve(L4, rD4, col, sol);
#pragma unroll
            for (int r = 0; r < 4; r++) YV[r][c] = sol[r];
        }
        ldl4_solve(L4, rD4, ru, ya);
        ldl4_solve(L4, rD4, rv, yb);

        float Sc[3][3], rcs[3];
#pragma unroll
        for (int i = 0; i < 3; i++) {
#pragma unroll
            for (int j = 0; j < 3; j++) {
                float v = Cm[i][j];
#pragma unroll
                for (int k = 0; k < 4; k++) v -= Ub[k][i] * YU[k][j] + Vb[k][i] * YV[k][j];
                Sc[i][j] = v;
            }
            float v = rc[i];
#pragma unroll
            for (int k = 0; k < 4; k++) v -= Ub[k][i] * ya[k] + Vb[k][i] * yb[k];
            rcs[i] = v;
        }
        float cv[3];
        ldl3_solve(Sc, rcs, cv);

        float av[4], bv[4];
#pragma unroll
        for (int r = 0; r < 4; r++) {
            av[r] = (ya[r] - (YU[r][0]*cv[0] + YU[r][1]*cv[1] + YU[r][2]*cv[2])) * 256.f;
            bv[r] = (yb[r] - (YV[r][0]*cv[0] + YV[r][1]*cv[1] + YV[r][2]*cv[2])) * 256.f;
        }

        float P[3][4] = {{av[0],av[1],av[2],av[3]},
                         {bv[0],bv[1],bv[2],bv[3]},
                         {cv[0],cv[1],cv[2],1.f}};

        float k00=sKq[0],k01=sKq[1],k02=sKq[2];
        float k10=sKq[3],k11=sKq[4],k12=sKq[5];
        float k20=sKq[6],k21=sKq[7],k22=sKq[8];
        float detK = k00*(k11*k22-k12*k21) - k01*(k10*k22-k12*k20) + k02*(k10*k21-k11*k20);
        float idk = __fdividef(1.f, detK);
        float iK[3][3] = {
            {(k11*k22-k12*k21)*idk, (k02*k21-k01*k22)*idk, (k01*k12-k02*k11)*idk},
            {(k12*k20-k10*k22)*idk, (k00*k22-k02*k20)*idk, (k02*k10-k00*k12)*idk},
            {(k10*k21-k11*k20)*idk, (k01*k20-k00*k21)*idk, (k00*k11-k01*k10)*idk}};

        float M[3][4];
#pragma unroll
        for (int i = 0; i < 3; i++)
#pragma unroll
            for (int j = 0; j < 4; j++)
                M[i][j] = iK[i][0]*P[0][j] + iK[i][1]*P[1][j] + iK[i][2]*P[2][j];

        float dM = M[0][0]*(M[1][1]*M[2][2]-M[1][2]*M[2][1])
                 - M[0][1]*(M[1][0]*M[2][2]-M[1][2]*M[2][0])
                 + M[0][2]*(M[1][0]*M[2][1]-M[1][1]*M[2][0]);
        float sg = (dM > 0.f) ? 1.f : ((dM < 0.f) ? -1.f : 0.f);
#pragma unroll
        for (int i = 0; i < 3; i++)
#pragma unroll
            for (int j = 0; j < 4; j++) M[i][j] *= sg;

        // determinant-scaled polar Newton (Higham) -> R
        float fro = 0.f;
#pragma unroll
        for (int i = 0; i < 3; i++)
#pragma unroll
            for (int j = 0; j < 3; j++) fro += M[i][j] * M[i][j];
        float s0i = rsqrtf(fmaxf(fro * (1.f/3.f), 1e-30f));
        float X00=M[0][0]*s0i, X01=M[0][1]*s0i, X02=M[0][2]*s0i;
        float X10=M[1][0]*s0i, X11=M[1][1]*s0i, X12=M[1][2]*s0i;
        float X20=M[2][0]*s0i, X21=M[2][1]*s0i, X22=M[2][2]*s0i;
#pragma unroll
        for (int it = 0; it < 6; it++) {
            float c00 = X11*X22 - X12*X21;
            float c01 = X12*X20 - X10*X22;
            float c02 = X10*X21 - X11*X20;
            float c10 = X02*X21 - X01*X22;
            float c11 = X00*X22 - X02*X20;
            float c12 = X01*X20 - X00*X21;
            float c20 = X01*X12 - X02*X11;
            float c21 = X02*X10 - X00*X12;
            float c22 = X00*X11 - X01*X10;
            float det = X00*c00 + X01*c01 + X02*c02;
            float g = 1.f, gi = 1.f;
            if (it < 3) {
                gi = cbrtf(fmaxf(fabsf(det), 1e-30f));
                g  = __fdividef(1.f, gi);
            }
            float rdet = __fdividef(0.5f * gi, det);
            float hg = 0.5f * g;
            X00 = hg*X00 + c00*rdet; X01 = hg*X01 + c01*rdet; X02 = hg*X02 + c02*rdet;
            X10 = hg*X10 + c10*rdet; X11 = hg*X11 + c11*rdet; X12 = hg*X12 + c12*rdet;
            X20 = hg*X20 + c20*rdet; X21 = hg*X21 + c21*rdet; X22 = hg*X22 + c22*rdet;
        }
        float trH = X00*M[0][0] + X01*M[0][1] + X02*M[0][2]
                  + X10*M[1][0] + X11*M[1][1] + X12*M[1][2]
                  + X20*M[2][0] + X21*M[2][1] + X22*M[2][2];
        float rmd = __fdividef(3.f, trH);
        float tp0 = M[0][3]*rmd, tp1 = M[1][3]*rmd, tp2 = M[2][3]*rmd;

        float tr = X00*sGt[0] + X01*sGt[1] + X02*sGt[2]
                 + X10*sGt[4] + X11*sGt[5] + X12*sGt[6]
                 + X20*sGt[8] + X21*sGt[9] + X22*sGt[10];
        float cosang = fminf(fmaxf((tr - 1.f) * 0.5f, -1.f + 1e-7f), 1.f - 1e-7f);
        float rot = acosf(cosang);
        float dx = tp0 - sGt[3];
        float dy = tp1 - sGt[7];
        float dz = tp2 - sGt[11];
        float terr = sqrtf(dx*dx + dy*dy + dz*dz);

        g_per[prob] = rot + terr;
        g_cnt[prob] = sMo[40];

        // fused final scalar: last block to finish reduces all 32 problems
        __threadfence();
        int tk = atomicAdd(&g_ticket, 1);
        if (tk == NPROB - 1) {
            __threadfence();
            float tot = 0.f, cnt = 0.f;
#pragma unroll
            for (int i = 0; i < NPROB; i++) {
                float c = (g_cnt[i] >= (float)MIN_CORR) ? 1.f : 0.f;
                tot += g_per[i] * c;
                cnt += c;
            }
            out[0] = tot / fmaxf(cnt, 1.f);
            g_ticket = 0;   // reset for next graph replay
        }
    }
}

extern "C" void kernel_launch(void* const* d_in, const int* in_sizes, int n_in,
                              void* d_out, int out_size) {
    const float* dense_b  = (const float*)d_in[1];
    const float* dense_w  = (const float*)d_in[2];
    const int*   pcls     = (const int*)  d_in[3];
    const float* Kmat     = (const float*)d_in[4];
    const float* poses    = (const float*)d_in[5];
    const float* gt       = (const float*)d_in[6];
    const float* depth    = (const float*)d_in[7];

    k_stream<<<4096, 256>>>(dense_b, dense_w, pcls, Kmat, poses, depth);
    k_solve<<<NPROB, 96>>>(Kmat, gt, (float*)d_out);
}